// round 9
// baseline (speedup 1.0000x reference)
#include <cuda_runtime.h>
#include <cuda_fp16.h>
#include <cstdint>

// ---------------------------------------------------------------------------
// Problem constants
// ---------------------------------------------------------------------------
#define B_ 4
#define N_ 4096
#define M_ 4096
#define C_ 512
#define R_ (B_ * N_)                     // 16384 rows
static const long NM_ = (long)N_ * M_;   // 16,777,216 per batch

// ---------------------------------------------------------------------------
// GEMM tiling: CTA 128(M)x64(N), BK=64, 8 warps (4x2), warp tile 32x32,
// 2-stage cp.async pipeline, 3 CTAs/SM (register budget 85).
// ---------------------------------------------------------------------------
#define BK 64
#define ROWB 144                  // 64 fp16 = 128B + 16B pad (conflict-free)
#define A_TILE (128 * ROWB)       // 18432 B
#define B_TILE (64 * ROWB)        //  9216 B
#define STAGE_B (A_TILE + B_TILE) // 27648 B
#define SMEM_B (2 * STAGE_B)      // 55296 B

__device__ __forceinline__ uint32_t smem_u32(const void* p) {
    uint32_t a;
    asm("{ .reg .u64 t; cvta.to.shared.u64 t, %1; cvt.u32.u64 %0, t; }" : "=r"(a) : "l"(p));
    return a;
}

#define LDSM4(r, addr) \
    asm volatile("ldmatrix.sync.aligned.m8n8.x4.shared.b16 {%0,%1,%2,%3}, [%4];" \
                 : "=r"((r)[0]), "=r"((r)[1]), "=r"((r)[2]), "=r"((r)[3]) : "r"(addr))

#define MMA(dd, aa, b0, b1) \
    asm volatile("mma.sync.aligned.m16n8k16.row.col.f32.f16.f16.f32 " \
                 "{%0,%1,%2,%3}, {%4,%5,%6,%7}, {%8,%9}, {%0,%1,%2,%3};" \
                 : "+f"((dd)[0]), "+f"((dd)[1]), "+f"((dd)[2]), "+f"((dd)[3]) \
                 : "r"((aa)[0]), "r"((aa)[1]), "r"((aa)[2]), "r"((aa)[3]), \
                   "r"(b0), "r"(b1))

#define CP16(saddr, gptr) \
    asm volatile("cp.async.cg.shared.global [%0], [%1], 16;" :: "r"(saddr), "l"(gptr))

// ---------------------------------------------------------------------------
// Scratch (__device__ globals; no dynamic allocation allowed)
// ---------------------------------------------------------------------------
__device__ __half g_rgb[R_ * C_];
__device__ __half g_dep[R_ * C_];
__device__ __half g_wt[3 * C_ * C_];             // W^T for q,k,v: [co][c]
__device__ __half g_q[R_ * C_];
__device__ __half g_k[R_ * C_];
__device__ __half g_vt[(long)B_ * C_ * M_];      // V^T per batch: [b][c][m]
__device__ __half g_p[(long)B_ * N_ * M_];       // unnormalized exp (128 MB)
__device__ float  g_partial[(long)R_ * 64];      // per (row, 64-coltile) exp sums
__device__ float  g_rinv[R_];                    // 1 / rowsum

// ---------------------------------------------------------------------------
// ONE conversion kernel: rgb->fp16, dep->fp16, Wq/Wk/Wv -> W^T fp16.
// ---------------------------------------------------------------------------
#define NIN (R_ * C_)                    // 8,388,608
#define NV4 (NIN / 4)
#define WCNT (C_ * C_)                   // 262,144 per weight

__global__ void __launch_bounds__(256) convert_all(
    const float* __restrict__ rgb, const float* __restrict__ dep,
    const float* __restrict__ Wq, const float* __restrict__ Wk,
    const float* __restrict__ Wv,
    __half* __restrict__ orgb, __half* __restrict__ odep,
    __half* __restrict__ owt)
{
    int i = blockIdx.x * blockDim.x + threadIdx.x;
    if (i < 2 * NV4) {
        const float4* src = (i < NV4) ? (const float4*)rgb : (const float4*)dep;
        __half* dst = (i < NV4) ? orgb : odep;
        int j = (i < NV4) ? i : i - NV4;
        float4 v = src[j];
        __half2 h0, h1;
        h0.x = __float2half_rn(v.x); h0.y = __float2half_rn(v.y);
        h1.x = __float2half_rn(v.z); h1.y = __float2half_rn(v.w);
        *(__half2*)(dst + j * 4)     = h0;
        *(__half2*)(dst + j * 4 + 2) = h1;
    } else {
        int j = i - 2 * NV4;
        if (j < 3 * WCNT) {
            const float* W = (j < WCNT) ? Wq : (j < 2 * WCNT) ? Wk : Wv;
            int t = (j < WCNT) ? j : (j < 2 * WCNT) ? j - WCNT : j - 2 * WCNT;
            int co = t >> 9, c = t & 511;
            owt[j] = __float2half_rn(W[c * C_ + co]);
        }
    }
}

// ---------------------------------------------------------------------------
// Rowsum reduce: 64 partials per row -> 1/sum
// ---------------------------------------------------------------------------
__global__ void rowsum_kernel(const float* __restrict__ partial,
                              float* __restrict__ rinv) {
    int i = blockIdx.x * blockDim.x + threadIdx.x;   // 0..R_-1
    const float4* p = (const float4*)(partial + (long)i * 64);
    float s = 0.f;
    #pragma unroll
    for (int j = 0; j < 16; j++) {
        float4 v = p[j];
        s += (v.x + v.y) + (v.z + v.w);
    }
    rinv[i] = 1.0f / s;
}

// ---------------------------------------------------------------------------
// fp16 GEMM: D[128x64] = sum_k A[rowtile,k] * B[coltile,k], K-major both.
// Modes:
//   0: out fp16, row-major [row, C_], +bias[col]
//   1: out fp16, transposed per batch [b][col][m], +bias[col]  (V^T)
//   2: P = exp(v*scale) fp16, [bz][row][col] ld=M_, + partial row sums
//   3: out fp32 * rinv[row],  [bz][row][col] ld=C_    (final output)
// ---------------------------------------------------------------------------
__global__ void __launch_bounds__(256, 3) gemm_f16(
    const __half* __restrict__ A, const __half* __restrict__ Bp,
    int Ktot, long aBatch, long bBatch,
    const float* __restrict__ bias, float outScale, int mode,
    float* __restrict__ outF, __half* __restrict__ outH,
    float* __restrict__ partial, const float* __restrict__ rinv)
{
    extern __shared__ char smem[];
    const uint32_t sb = smem_u32(smem);
    const int tid = threadIdx.x, lane = tid & 31, wid = tid >> 5;
    const int wm = wid >> 1, wn = wid & 1;          // warp grid 4(M) x 2(N)
    const int bx = blockIdx.x, by = blockIdx.y, bz = blockIdx.z;

    // ---- cp.async assignment
    // A tile: 128 rows x 128B; thread -> (row = tid>>1, 64B half), 4x CP16
    const int arow = tid >> 1, ahalf = tid & 1;
    const __half* pA = A + bz * aBatch + (long)(bx * 128 + arow) * Ktot + ahalf * 32;
    const uint32_t sstA = sb + (uint32_t)arow * ROWB + ahalf * 64;
    // B tile: 64 rows x 128B; thread -> (row = tid>>2, 32B quarter), 2x CP16
    const int brow = tid >> 2, bq = tid & 3;
    const __half* pB = Bp + bz * bBatch + (long)(by * 64 + brow) * Ktot + bq * 16;
    const uint32_t sstB = sb + A_TILE + (uint32_t)brow * ROWB + bq * 32;

    const int kIters = Ktot / BK;

    auto issue = [&](int kt, int stage) {
        const uint32_t so = stage * STAGE_B;
        const int off = kt * BK;
        #pragma unroll
        for (int c = 0; c < 4; c++)
            CP16(sstA + so + c * 16, pA + off + c * 8);
        CP16(sstB + so,      pB + off);
        CP16(sstB + so + 16, pB + off + 8);
    };

    float d[2][4][4];
    #pragma unroll
    for (int i = 0; i < 2; i++)
        #pragma unroll
        for (int j = 0; j < 4; j++)
            #pragma unroll
            for (int e = 0; e < 4; e++) d[i][j][e] = 0.f;

    issue(0, 0);
    asm volatile("cp.async.commit_group;" ::: "memory");

    for (int kt = 0; kt < kIters; kt++) {
        asm volatile("cp.async.wait_group 0;" ::: "memory");
        __syncthreads();
        if (kt + 1 < kIters) {
            issue(kt + 1, (kt + 1) & 1);
            asm volatile("cp.async.commit_group;" ::: "memory");
        }

        const uint32_t st = sb + (kt & 1) * STAGE_B;
        #pragma unroll
        for (int s = 0; s < 4; s++) {                // four k16 steps per BK=64
            uint32_t ah[2][4], bh[4][2];
            const uint32_t coff = s * 32 + (lane >> 4) * 16;
            const uint32_t rowA = wm * 32 + (lane & 15);
            #pragma unroll
            for (int mt = 0; mt < 2; mt++)
                LDSM4(ah[mt], st + (rowA + mt * 16) * ROWB + coff);
            const uint32_t rowB = wn * 32 + (lane & 15);
            #pragma unroll
            for (int np = 0; np < 2; np++) {
                uint32_t r[4];
                LDSM4(r, st + A_TILE + (rowB + np * 16) * ROWB + coff);
                bh[2 * np][0] = r[0]; bh[2 * np][1] = r[2];
                bh[2 * np + 1][0] = r[1]; bh[2 * np + 1][1] = r[3];
            }
            #pragma unroll
            for (int mt = 0; mt < 2; mt++)
                #pragma unroll
                for (int nt = 0; nt < 4; nt++)
                    MMA(d[mt][nt], ah[mt], bh[nt][0], bh[nt][1]);
        }
    }

    // ---- epilogue
    const int mbase = bx * 128 + wm * 32;
    const int nbase = by * 64 + wn * 32;
    const int lr = lane >> 2;            // 0..7
    const int lc = (lane & 3) * 2;       // 0,2,4,6

    float esum[2][2];
    esum[0][0] = esum[0][1] = esum[1][0] = esum[1][1] = 0.f;

    #pragma unroll
    for (int mt = 0; mt < 2; mt++) {
        #pragma unroll
        for (int nt = 0; nt < 4; nt++) {
            #pragma unroll
            for (int h = 0; h < 2; h++) {
                const int m = mbase + mt * 16 + lr + h * 8;
                const int n = nbase + nt * 8 + lc;
                float v0 = d[mt][nt][h * 2 + 0];
                float v1 = d[mt][nt][h * 2 + 1];
                if (mode == 0) {
                    v0 += bias[n]; v1 += bias[n + 1];
                    __half2 hv;
                    hv.x = __float2half_rn(v0); hv.y = __float2half_rn(v1);
                    *(__half2*)(outH + (long)m * C_ + n) = hv;
                } else if (mode == 1) {
                    v0 += bias[n]; v1 += bias[n + 1];
                    const int b = m >> 12, mm = m & 4095;
                    const long idx = (long)b * ((long)C_ * M_) + (long)n * M_ + mm;
                    outH[idx]      = __float2half_rn(v0);
                    outH[idx + M_] = __float2half_rn(v1);
                } else if (mode == 2) {
                    float e0 = __expf(v0 * outScale);
                    float e1 = __expf(v1 * outScale);
                    esum[mt][h] += e0 + e1;
                    __half2 hv;
                    hv.x = __float2half_rn(e0); hv.y = __float2half_rn(e1);
                    *(__half2*)(outH + (long)bz * NM_ + (long)m * M_ + n) = hv;
                } else {
                    const float r = rinv[bz * N_ + m];
                    const long idx = (long)bz * ((long)N_ * C_) + (long)m * C_ + n;
                    float2 v; v.x = v0 * r; v.y = v1 * r;
                    *(float2*)(outF + idx) = v;
                }
            }
        }
    }

    if (mode == 2) {
        // deterministic partial row sums: lane reduce -> smem -> global
        __syncthreads();                 // mainloop smem reads complete
        float* sred = (float*)smem;      // [2 warp-cols][128 rows]
        #pragma unroll
        for (int mt = 0; mt < 2; mt++) {
            #pragma unroll
            for (int h = 0; h < 2; h++) {
                float v = esum[mt][h];
                v += __shfl_xor_sync(0xFFFFFFFFu, v, 1);
                v += __shfl_xor_sync(0xFFFFFFFFu, v, 2);
                if ((lane & 3) == 0)
                    sred[wn * 128 + wm * 32 + mt * 16 + h * 8 + lr] = v;
            }
        }
        __syncthreads();
        if (tid < 128) {
            float s = sred[tid] + sred[128 + tid];
            partial[((long)(bz * N_ + bx * 128 + tid)) * 64 + by] = s;
        }
    }
}

// ---------------------------------------------------------------------------
// Host launch.  Launch order: 1 convert, 2-4 proj, 5 SCORES (ncu), 6 rowsum, 7 PV
// ---------------------------------------------------------------------------
extern "C" void kernel_launch(void* const* d_in, const int* in_sizes, int n_in,
                              void* d_out, int out_size) {
    (void)in_sizes; (void)n_in; (void)out_size;
    const float* rgb = (const float*)d_in[0];
    const float* dep = (const float*)d_in[1];
    const float* Wq  = (const float*)d_in[2];
    const float* bq  = (const float*)d_in[3];
    const float* Wk  = (const float*)d_in[4];
    const float* bk  = (const float*)d_in[5];
    const float* Wv  = (const float*)d_in[6];
    const float* bv  = (const float*)d_in[7];
    float* out = (float*)d_out;

    void* p;
    __half *rgb_h, *dep_h, *wt, *q, *k, *vt, *ph;
    float *partial, *rinv;
    cudaGetSymbolAddress(&p, g_rgb);     rgb_h   = (__half*)p;
    cudaGetSymbolAddress(&p, g_dep);     dep_h   = (__half*)p;
    cudaGetSymbolAddress(&p, g_wt);      wt      = (__half*)p;
    cudaGetSymbolAddress(&p, g_q);       q       = (__half*)p;
    cudaGetSymbolAddress(&p, g_k);       k       = (__half*)p;
    cudaGetSymbolAddress(&p, g_vt);      vt      = (__half*)p;
    cudaGetSymbolAddress(&p, g_p);       ph      = (__half*)p;
    cudaGetSymbolAddress(&p, g_partial); partial = (float*)p;
    cudaGetSymbolAddress(&p, g_rinv);    rinv    = (float*)p;

    cudaFuncSetAttribute(gemm_f16, cudaFuncAttributeMaxDynamicSharedMemorySize, SMEM_B);

    // Launch 1: all conversions
    const int workItems = 2 * NV4 + 3 * WCNT;
    convert_all<<<(workItems + 255) / 256, 256>>>(rgb, dep, Wq, Wk, Wv,
                                                  rgb_h, dep_h, wt);

    // Launches 2-4: QKV projections  [16384,512] x [512,512]^T (+bias)
    dim3 gProj(R_ / 128, C_ / 64, 1);   // (128, 8)
    gemm_f16<<<gProj, 256, SMEM_B>>>(rgb_h, wt,
        C_, 0, 0, bq, 1.f, 0, nullptr, q, nullptr, nullptr);
    gemm_f16<<<gProj, 256, SMEM_B>>>(dep_h, wt + C_ * C_,
        C_, 0, 0, bk, 1.f, 0, nullptr, k, nullptr, nullptr);
    gemm_f16<<<gProj, 256, SMEM_B>>>(dep_h, wt + 2 * C_ * C_,
        C_, 0, 0, bv, 1.f, 1, nullptr, vt, nullptr, nullptr);   // V^T

    // Launch 5 (ncu target): scores + exp fused
    dim3 gS(N_ / 128, M_ / 64, B_);   // (32, 64, 4)
    gemm_f16<<<gS, 256, SMEM_B>>>(q, k,
        C_, (long)N_ * C_, (long)M_ * C_, nullptr, 0.044194173824159216f, 2,
        nullptr, ph, partial, nullptr);

    // Launch 6: rowsum -> 1/sum
    rowsum_kernel<<<R_ / 256, 256>>>(partial, rinv);

    // Launch 7: O = (P V) * rinv[row]
    dim3 gO(N_ / 128, C_ / 64, B_);   // (32, 8, 4)
    gemm_f16<<<gO, 256, SMEM_B>>>(ph, vt,
        M_, NM_, (long)C_ * M_, nullptr, 1.f, 3,
        out, nullptr, nullptr, rinv);
}